// round 1
// baseline (speedup 1.0000x reference)
#include <cuda_runtime.h>
#include <cstdint>

#define N_NODES 50000
#define DIM 512
#define NCOL 1024
#define KDIM 512

typedef unsigned long long ull;

// ---------------- scratch (static device globals; no allocation) ----------------
__device__ __align__(16) float g_B1[KDIM * NCOL];                 // 2 MB  packed [Ws1^T | Wn1^T]
__device__ __align__(16) float g_B2[KDIM * NCOL];                 // 2 MB  packed [Ws2^T | Wn2^T]
__device__ __align__(16) float g_C[(size_t)N_NODES * NCOL];       // 204.8 MB  [Y | Z] per layer
__device__ __align__(16) float g_H1[(size_t)N_NODES * DIM];       // 102.4 MB  layer-1 output
__device__ float g_part[2 * N_NODES];                             // per-node FC partial dots

// ---------------- weight repack: Bpack[k][j] ----------------
// j <  512 : W[j][k]        (self part)
// j >= 512 : W[j-512][512+k] (neighbor part)
__global__ void pack_kernel(const float* __restrict__ W1, const float* __restrict__ W2) {
    int idx = blockIdx.x * blockDim.x + threadIdx.x;
    if (idx >= KDIM * NCOL) return;
    int k = idx >> 10;
    int j = idx & 1023;
    int src = (j < DIM) ? (j * NCOL + k) : ((j - DIM) * NCOL + DIM + k);
    g_B1[idx] = W1[src];
    g_B2[idx] = W2[src];
}

// ---------------- SGEMM: C[M,1024] = A[M,512] @ Bpack[512,1024] ----------------
// 128x128x8 tile, 256 threads, 8x8 per-thread microtile held as f32x2 pairs
// along M. Inner product uses packed fma.rn.f32x2 (2 FMA/lane/instr on sm_103a).
#define BM 128
#define BN 128
#define BK 8

__global__ __launch_bounds__(256, 2)
void sgemm_kernel(const float* __restrict__ Aext, int layer, int M) {
    const float* __restrict__ A  = (layer == 0) ? Aext : g_H1;
    const float* __restrict__ Bm = (layer == 0) ? g_B1 : g_B2;

    __shared__ __align__(16) float As[BK][BM + 4];   // [k][m], padded
    __shared__ __align__(16) float Bs[BK][BN];       // [k][n]

    const int tid = threadIdx.x;
    const int tx = tid & 15;          // n-dir (16)
    const int ty = tid >> 4;          // m-dir (16)
    const int mBase = blockIdx.y * BM;
    const int nBase = blockIdx.x * BN;

    const int loadArow = tid >> 1;           // 0..127
    const int loadAcol = (tid & 1) * 4;      // 0 or 4
    const int loadBrow = tid >> 5;           // 0..7
    const int loadBcol = (tid & 31) * 4;     // 0..124

    ull acc[4][8];
    #pragma unroll
    for (int i = 0; i < 4; i++)
        #pragma unroll
        for (int j = 0; j < 8; j++) acc[i][j] = 0ull;

    const bool aValid = (mBase + loadArow) < M;
    const float* Ap = A + (size_t)(mBase + loadArow) * KDIM + loadAcol;
    const float* Bp = Bm + (size_t)loadBrow * NCOL + nBase + loadBcol;

    for (int k0 = 0; k0 < KDIM; k0 += BK) {
        float4 av = make_float4(0.f, 0.f, 0.f, 0.f);
        if (aValid) av = *(const float4*)(Ap + k0);
        float4 bv = *(const float4*)(Bp + (size_t)k0 * NCOL);

        As[loadAcol + 0][loadArow] = av.x;
        As[loadAcol + 1][loadArow] = av.y;
        As[loadAcol + 2][loadArow] = av.z;
        As[loadAcol + 3][loadArow] = av.w;
        *(float4*)&Bs[loadBrow][loadBcol] = bv;
        __syncthreads();

        #pragma unroll
        for (int k = 0; k < BK; k++) {
            // A pairs along M: (m, m+1) as one 64-bit word
            ull a2[4];
            const ull* ap = (const ull*)&As[k][ty * 8];
            #pragma unroll
            for (int i = 0; i < 4; i++) a2[i] = ap[i];

            // B: 8 scalars, splat each into both lanes
            const float4* bp4 = (const float4*)&Bs[k][tx * 8];
            float4 b0 = bp4[0], b1 = bp4[1];
            float bcol[8] = {b0.x, b0.y, b0.z, b0.w, b1.x, b1.y, b1.z, b1.w};
            ull b2[8];
            #pragma unroll
            for (int j = 0; j < 8; j++)
                asm("mov.b64 %0, {%1, %2};" : "=l"(b2[j]) : "f"(bcol[j]), "f"(bcol[j]));

            #pragma unroll
            for (int i = 0; i < 4; i++)
                #pragma unroll
                for (int j = 0; j < 8; j++)
                    asm("fma.rn.f32x2 %0, %1, %2, %0;"
                        : "+l"(acc[i][j]) : "l"(a2[i]), "l"(b2[j]));
        }
        __syncthreads();
    }

    // store: acc[i][j] = (row 2i, row 2i+1) for column tx*8+j
    #pragma unroll
    for (int i = 0; i < 4; i++) {
        int r0 = mBase + ty * 8 + 2 * i;
        if (r0 >= M) continue;
        float lo[8], hi[8];
        #pragma unroll
        for (int j = 0; j < 8; j++)
            asm("mov.b64 {%0, %1}, %2;" : "=f"(lo[j]), "=f"(hi[j]) : "l"(acc[i][j]));
        float* c0 = g_C + (size_t)r0 * NCOL + nBase + tx * 8;
        *(float4*)(c0 + 0) = make_float4(lo[0], lo[1], lo[2], lo[3]);
        *(float4*)(c0 + 4) = make_float4(lo[4], lo[5], lo[6], lo[7]);
        if (r0 + 1 < M) {
            float* c1 = c0 + NCOL;
            *(float4*)(c1 + 0) = make_float4(hi[0], hi[1], hi[2], hi[3]);
            *(float4*)(c1 + 4) = make_float4(hi[4], hi[5], hi[6], hi[7]);
        }
    }
}

// ---------------- layer-1 combine: h1 = relu(Y_i + 0.5*(Z_n0 + Z_n1)) ----------------
__global__ void combine1_kernel(const int* __restrict__ neighs) {
    int i = blockIdx.x;
    int n0 = neighs[2 * i], n1 = neighs[2 * i + 1];
    int j = threadIdx.x * 4;   // 128 threads cover 512
    float4 s  = *(const float4*)(g_C + (size_t)i  * NCOL + j);
    float4 z0 = *(const float4*)(g_C + (size_t)n0 * NCOL + DIM + j);
    float4 z1 = *(const float4*)(g_C + (size_t)n1 * NCOL + DIM + j);
    float4 o;
    o.x = fmaxf(fmaf(0.5f, z0.x + z1.x, s.x), 0.f);
    o.y = fmaxf(fmaf(0.5f, z0.y + z1.y, s.y), 0.f);
    o.z = fmaxf(fmaf(0.5f, z0.z + z1.z, s.z), 0.f);
    o.w = fmaxf(fmaf(0.5f, z0.w + z1.w, s.w), 0.f);
    *(float4*)(g_H1 + (size_t)i * DIM + j) = o;
}

// ---------------- layer-2 combine fused with FC-head partial dots ----------------
__global__ void combine2_kernel(const int* __restrict__ neighs,
                                const float* __restrict__ fcw,
                                float* __restrict__ out) {
    int i = blockIdx.x;
    int tid = threadIdx.x;
    int j = tid * 4;
    int n0 = neighs[2 * i], n1 = neighs[2 * i + 1];
    float4 s  = *(const float4*)(g_C + (size_t)i  * NCOL + j);
    float4 z0 = *(const float4*)(g_C + (size_t)n0 * NCOL + DIM + j);
    float4 z1 = *(const float4*)(g_C + (size_t)n1 * NCOL + DIM + j);
    float4 o;
    o.x = fmaxf(fmaf(0.5f, z0.x + z1.x, s.x), 0.f);
    o.y = fmaxf(fmaf(0.5f, z0.y + z1.y, s.y), 0.f);
    o.z = fmaxf(fmaf(0.5f, z0.z + z1.z, s.z), 0.f);
    o.w = fmaxf(fmaf(0.5f, z0.w + z1.w, s.w), 0.f);
    size_t idx = (size_t)i * DIM + j;
    *(float4*)(out + idx) = o;

    float4 w0 = *(const float4*)(fcw + idx);
    float4 w1 = *(const float4*)(fcw + (size_t)N_NODES * DIM + idx);
    float p0 = o.x * w0.x + o.y * w0.y + o.z * w0.z + o.w * w0.w;
    float p1 = o.x * w1.x + o.y * w1.y + o.z * w1.z + o.w * w1.w;

    __shared__ float s0[128], s1[128];
    s0[tid] = p0; s1[tid] = p1;
    __syncthreads();
    #pragma unroll
    for (int st = 64; st > 0; st >>= 1) {
        if (tid < st) { s0[tid] += s0[tid + st]; s1[tid] += s1[tid + st]; }
        __syncthreads();
    }
    if (tid == 0) { g_part[i] = s0[0]; g_part[N_NODES + i] = s1[0]; }
}

// ---------------- final: deterministic reduce + bias + log_softmax ----------------
__global__ void final_kernel(const float* __restrict__ fcb, float* __restrict__ out2) {
    __shared__ float s0[256], s1[256];
    int tid = threadIdx.x;
    float a = 0.f, b = 0.f;
    for (int i = tid; i < N_NODES; i += 256) { a += g_part[i]; b += g_part[N_NODES + i]; }
    s0[tid] = a; s1[tid] = b;
    __syncthreads();
    #pragma unroll
    for (int st = 128; st > 0; st >>= 1) {
        if (tid < st) { s0[tid] += s0[tid + st]; s1[tid] += s1[tid + st]; }
        __syncthreads();
    }
    if (tid == 0) {
        float l0 = s0[0] + fcb[0];
        float l1 = s1[0] + fcb[1];
        float m = fmaxf(l0, l1);
        float lse = m + logf(expf(l0 - m) + expf(l1 - m));
        out2[0] = l0 - lse;
        out2[1] = l1 - lse;
    }
}

// ---------------- launch ----------------
extern "C" void kernel_launch(void* const* d_in, const int* in_sizes, int n_in,
                              void* d_out, int out_size) {
    const float* x   = (const float*)d_in[0];
    const int*   nb1 = (const int*)  d_in[1];
    const int*   nb2 = (const int*)  d_in[2];
    const float* W1  = (const float*)d_in[3];
    const float* W2  = (const float*)d_in[4];
    const float* fcw = (const float*)d_in[5];
    const float* fcb = (const float*)d_in[6];
    float* out = (float*)d_out;

    pack_kernel<<<(KDIM * NCOL + 255) / 256, 256>>>(W1, W2);

    dim3 grid(NCOL / BN, (N_NODES + BM - 1) / BM);
    sgemm_kernel<<<grid, 256>>>(x, 0, N_NODES);          // layer 1: [Y1 | Z1] -> g_C
    combine1_kernel<<<N_NODES, 128>>>(nb1);              // -> g_H1
    sgemm_kernel<<<grid, 256>>>(nullptr, 1, N_NODES);    // layer 2: [Y2 | Z2] -> g_C
    combine2_kernel<<<N_NODES, 128>>>(nb2, fcw, out);    // flat -> d_out, FC partials
    final_kernel<<<1, 256>>>(fcb, out + (size_t)(out_size - 2));
}

// round 4
// speedup vs baseline: 2.3527x; 2.3527x over previous
#include <cuda_runtime.h>
#include <cuda_bf16.h>
#include <cstdint>

#define NN 50000
#define NPAD 50176          // 392 * 128
#define DIM 512
#define NCOL 1024
#define K3 1536             // [Ah|Ah|Al] x [Bh|Bl|Bh]
#define BM 128
#define BN 128
#define BK 64               // bf16 per k-chunk = 128 bytes per row
#define CHUNKS 24           // K3 / BK
#define STAGES 3
#define STAGE_BYTES 32768   // A 16KB + B 16KB
#define SMEM_TOTAL (STAGES * STAGE_BYTES)

typedef unsigned long long ull;

// ---------------- static device scratch (no allocation) ----------------
__device__ __align__(16) __nv_bfloat16 g_Ahl[(size_t)NPAD * K3];   // 154 MB
__device__ __align__(16) __nv_bfloat16 g_B1p[NCOL * K3];           // 3 MB
__device__ __align__(16) __nv_bfloat16 g_B2p[NCOL * K3];           // 3 MB
__device__ __align__(16) float g_C[(size_t)NPAD * NCOL];           // 205 MB
__device__ float g_part[2 * NN];

// ---------------- PTX helpers ----------------
__device__ __forceinline__ uint32_t smem_u32(const void* p) {
    uint32_t a;
    asm("{ .reg .u64 t; cvta.to.shared.u64 t, %1; cvt.u32.u64 %0, t; }" : "=r"(a) : "l"(p));
    return a;
}
#define CP16(dst, src) asm volatile("cp.async.cg.shared.global [%0], [%1], 16;" :: "r"(dst), "l"(src))
#define CP_COMMIT()    asm volatile("cp.async.commit_group;" ::: "memory")
#define CP_WAIT(n)     asm volatile("cp.async.wait_group %0;" :: "n"(n) : "memory")

#define LDSM_X4(r0, r1, r2, r3, a) \
    asm volatile("ldmatrix.sync.aligned.m8n8.x4.shared.b16 {%0,%1,%2,%3}, [%4];" \
        : "=r"(r0), "=r"(r1), "=r"(r2), "=r"(r3) : "r"(a))

#define MMA16816(c, a, b) \
    asm volatile("mma.sync.aligned.m16n8k16.row.col.f32.bf16.bf16.f32 " \
        "{%0,%1,%2,%3}, {%4,%5,%6,%7}, {%8,%9}, {%0,%1,%2,%3};" \
        : "+f"((c)[0]), "+f"((c)[1]), "+f"((c)[2]), "+f"((c)[3]) \
        : "r"((a)[0]), "r"((a)[1]), "r"((a)[2]), "r"((a)[3]), "r"((b)[0]), "r"((b)[1]))

// ---------------- split helper ----------------
__device__ __forceinline__ void split4(const float* v, __nv_bfloat16* h, __nv_bfloat16* l) {
    #pragma unroll
    for (int q = 0; q < 4; q++) {
        h[q] = __float2bfloat16(v[q]);
        l[q] = __float2bfloat16(v[q] - __bfloat162float(h[q]));
    }
}

// ---------------- weight pack: B'[n][k'] = [Bh | Bl | Bh], bf16 split ----------------
__global__ void packw_kernel(const float* __restrict__ W1, const float* __restrict__ W2) {
    int idx = blockIdx.x * blockDim.x + threadIdx.x;
    if (idx >= NCOL * DIM) return;
    int n = idx >> 9, k = idx & 511;
    int src = (n < DIM) ? (n * NCOL + k) : ((n - DIM) * NCOL + DIM + k);
    float v1 = W1[src], v2 = W2[src];
    __nv_bfloat16 h1 = __float2bfloat16(v1);
    __nv_bfloat16 l1 = __float2bfloat16(v1 - __bfloat162float(h1));
    __nv_bfloat16 h2 = __float2bfloat16(v2);
    __nv_bfloat16 l2 = __float2bfloat16(v2 - __bfloat162float(h2));
    size_t base = (size_t)n * K3;
    g_B1p[base + k] = h1; g_B1p[base + DIM + k] = l1; g_B1p[base + 2 * DIM + k] = h1;
    g_B2p[base + k] = h2; g_B2p[base + DIM + k] = l2; g_B2p[base + 2 * DIM + k] = h2;
}

// ---------------- convert x -> A' = [Ah | Ah | Al] ----------------
__global__ void convert_x_kernel(const float* __restrict__ x) {
    int i = blockIdx.x;
    int j = threadIdx.x * 4;                       // 128 threads cover 512
    __nv_bfloat16* row = g_Ahl + (size_t)i * K3;
    if (i >= NN) {
        *(ull*)(row + j) = 0ull; *(ull*)(row + DIM + j) = 0ull; *(ull*)(row + 2 * DIM + j) = 0ull;
        return;
    }
    float4 v4 = *(const float4*)(x + (size_t)i * DIM + j);
    float v[4] = {v4.x, v4.y, v4.z, v4.w};
    __nv_bfloat16 h[4], l[4];
    split4(v, h, l);
    *(ull*)(row + j) = *(ull*)h;
    *(ull*)(row + DIM + j) = *(ull*)h;
    *(ull*)(row + 2 * DIM + j) = *(ull*)l;
}

// ---------------- bf16 HMMA GEMM: g_C[M,1024] = A'[M,1536] @ B'^T ----------------
// CTA 128x128x64, 3-stage cp.async pipeline, 8 warps (2m x 4n), warp tile 64x32.
__global__ __launch_bounds__(256, 2) void gemm_kernel(int layer) {
    extern __shared__ __align__(1024) char smem[];
    const uint32_t sbase = smem_u32(smem);
    const int tid = threadIdx.x;
    const int wid = tid >> 5;
    const int lane = tid & 31;
    const int wm = wid & 1;           // 2 warps along M
    const int wn = wid >> 1;          // 4 warps along N
    const __nv_bfloat16* __restrict__ Bp = layer ? g_B2p : g_B1p;
    const size_t mBase = (size_t)blockIdx.y * BM;
    const int nBase = blockIdx.x * BN;

    const char* gA0 = (const char*)g_Ahl + mBase * (K3 * 2);
    const char* gB0 = (const char*)Bp + (size_t)nBase * (K3 * 2);

    // per-thread load offsets: 4 16B units for A, 4 for B per chunk
    auto load_chunk = [&](int kc, int s) {
        uint32_t sA = sbase + s * STAGE_BYTES;
        uint32_t sB = sA + 16384;
        const char* gA = gA0 + kc * 128;
        const char* gB = gB0 + kc * 128;
        #pragma unroll
        for (int i = 0; i < 4; i++) {
            int u = tid + i * 256;            // 0..1023
            int r = u >> 3, c = u & 7;
            uint32_t sw = (uint32_t)(r * 128 + (((c ^ (r & 7))) << 4));
            CP16(sA + sw, gA + (size_t)r * 3072 + c * 16);
            CP16(sB + sw, gB + (size_t)r * 3072 + c * 16);
        }
    };

    float acc[4][4][4];
    #pragma unroll
    for (int i = 0; i < 4; i++)
        #pragma unroll
        for (int j = 0; j < 4; j++)
            #pragma unroll
            for (int q = 0; q < 4; q++) acc[i][j][q] = 0.f;

    load_chunk(0, 0); CP_COMMIT();
    load_chunk(1, 1); CP_COMMIT();

    // precomputed ldmatrix lane rows
    const int lrow = lane & 15;       // row within 16
    const int lhalf = lane >> 4;      // k-half (0: k0-7, 1: k8-15)

    for (int kc = 0; kc < CHUNKS; kc++) {
        if (kc + 2 < CHUNKS) load_chunk(kc + 2, (kc + 2) % STAGES);
        CP_COMMIT();
        CP_WAIT(2);
        __syncthreads();

        uint32_t sA = sbase + (kc % STAGES) * STAGE_BYTES;
        uint32_t sB = sA + 16384;

        #pragma unroll
        for (int ks = 0; ks < 4; ks++) {
            uint32_t af[4][4], bf[4][2];
            #pragma unroll
            for (int am = 0; am < 4; am++) {
                int row = wm * 64 + am * 16 + lrow;
                int grp = ks * 2 + lhalf;
                uint32_t addr = sA + row * 128 + (((grp ^ (row & 7))) << 4);
                LDSM_X4(af[am][0], af[am][1], af[am][2], af[am][3], addr);
            }
            #pragma unroll
            for (int p = 0; p < 2; p++) {
                int row = wn * 32 + p * 16 + lrow;
                int grp = ks * 2 + lhalf;
                uint32_t addr = sB + row * 128 + (((grp ^ (row & 7))) << 4);
                uint32_t r0, r1, r2, r3;
                LDSM_X4(r0, r1, r2, r3, addr);
                bf[p * 2 + 0][0] = r0; bf[p * 2 + 0][1] = r2;
                bf[p * 2 + 1][0] = r1; bf[p * 2 + 1][1] = r3;
            }
            #pragma unroll
            for (int am = 0; am < 4; am++)
                #pragma unroll
                for (int bn = 0; bn < 4; bn++)
                    MMA16816(acc[am][bn], af[am], bf[bn]);
        }
        __syncthreads();
    }

    // epilogue: c frag m16n8 -> (row = l>>2 [+8], col = (l&3)*2)
    const int crow = lane >> 2;
    const int ccol = (lane & 3) * 2;
    #pragma unroll
    for (int am = 0; am < 4; am++) {
        size_t r0 = mBase + wm * 64 + am * 16 + crow;
        #pragma unroll
        for (int bn = 0; bn < 4; bn++) {
            int c0 = nBase + wn * 32 + bn * 8 + ccol;
            float* p0 = g_C + r0 * NCOL + c0;
            float* p1 = p0 + 8 * NCOL;
            *(float2*)p0 = make_float2(acc[am][bn][0], acc[am][bn][1]);
            *(float2*)p1 = make_float2(acc[am][bn][2], acc[am][bn][3]);
        }
    }
}

// ---------------- layer-1 combine + bf16 re-split: A' <- relu(Y + 0.5*(Z0+Z1)) ----------------
__global__ void combine1_kernel(const int* __restrict__ neighs) {
    int i = blockIdx.x;
    int j = threadIdx.x * 4;
    __nv_bfloat16* row = g_Ahl + (size_t)i * K3;
    if (i >= NN) {
        *(ull*)(row + j) = 0ull; *(ull*)(row + DIM + j) = 0ull; *(ull*)(row + 2 * DIM + j) = 0ull;
        return;
    }
    int n0 = neighs[2 * i], n1 = neighs[2 * i + 1];
    float4 s  = *(const float4*)(g_C + (size_t)i  * NCOL + j);
    float4 z0 = *(const float4*)(g_C + (size_t)n0 * NCOL + DIM + j);
    float4 z1 = *(const float4*)(g_C + (size_t)n1 * NCOL + DIM + j);
    float v[4];
    v[0] = fmaxf(fmaf(0.5f, z0.x + z1.x, s.x), 0.f);
    v[1] = fmaxf(fmaf(0.5f, z0.y + z1.y, s.y), 0.f);
    v[2] = fmaxf(fmaf(0.5f, z0.z + z1.z, s.z), 0.f);
    v[3] = fmaxf(fmaf(0.5f, z0.w + z1.w, s.w), 0.f);
    __nv_bfloat16 h[4], l[4];
    split4(v, h, l);
    *(ull*)(row + j) = *(ull*)h;
    *(ull*)(row + DIM + j) = *(ull*)h;
    *(ull*)(row + 2 * DIM + j) = *(ull*)l;
}

// ---------------- layer-2 combine fused with FC-head partial dots ----------------
__global__ void combine2_kernel(const int* __restrict__ neighs,
                                const float* __restrict__ fcw,
                                float* __restrict__ out) {
    int i = blockIdx.x;
    int tid = threadIdx.x;
    int j = tid * 4;
    int n0 = neighs[2 * i], n1 = neighs[2 * i + 1];
    float4 s  = *(const float4*)(g_C + (size_t)i  * NCOL + j);
    float4 z0 = *(const float4*)(g_C + (size_t)n0 * NCOL + DIM + j);
    float4 z1 = *(const float4*)(g_C + (size_t)n1 * NCOL + DIM + j);
    float4 o;
    o.x = fmaxf(fmaf(0.5f, z0.x + z1.x, s.x), 0.f);
    o.y = fmaxf(fmaf(0.5f, z0.y + z1.y, s.y), 0.f);
    o.z = fmaxf(fmaf(0.5f, z0.z + z1.z, s.z), 0.f);
    o.w = fmaxf(fmaf(0.5f, z0.w + z1.w, s.w), 0.f);
    size_t idx = (size_t)i * DIM + j;
    *(float4*)(out + idx) = o;

    float4 w0 = *(const float4*)(fcw + idx);
    float4 w1 = *(const float4*)(fcw + (size_t)NN * DIM + idx);
    float p0 = o.x * w0.x + o.y * w0.y + o.z * w0.z + o.w * w0.w;
    float p1 = o.x * w1.x + o.y * w1.y + o.z * w1.z + o.w * w1.w;

    __shared__ float s0[128], s1[128];
    s0[tid] = p0; s1[tid] = p1;
    __syncthreads();
    #pragma unroll
    for (int st = 64; st > 0; st >>= 1) {
        if (tid < st) { s0[tid] += s0[tid + st]; s1[tid] += s1[tid + st]; }
        __syncthreads();
    }
    if (tid == 0) { g_part[i] = s0[0]; g_part[NN + i] = s1[0]; }
}

// ---------------- final: deterministic reduce + bias + log_softmax ----------------
__global__ void final_kernel(const float* __restrict__ fcb, float* __restrict__ out2) {
    __shared__ float s0[256], s1[256];
    int tid = threadIdx.x;
    float a = 0.f, b = 0.f;
    for (int i = tid; i < NN; i += 256) { a += g_part[i]; b += g_part[NN + i]; }
    s0[tid] = a; s1[tid] = b;
    __syncthreads();
    #pragma unroll
    for (int st = 128; st > 0; st >>= 1) {
        if (tid < st) { s0[tid] += s0[tid + st]; s1[tid] += s1[tid + st]; }
        __syncthreads();
    }
    if (tid == 0) {
        float l0 = s0[0] + fcb[0];
        float l1 = s1[0] + fcb[1];
        float m = fmaxf(l0, l1);
        float lse = m + logf(expf(l0 - m) + expf(l1 - m));
        out2[0] = l0 - lse;
        out2[1] = l1 - lse;
    }
}

// ---------------- launch ----------------
extern "C" void kernel_launch(void* const* d_in, const int* in_sizes, int n_in,
                              void* d_out, int out_size) {
    const float* x   = (const float*)d_in[0];
    const int*   nb1 = (const int*)  d_in[1];
    const int*   nb2 = (const int*)  d_in[2];
    const float* W1  = (const float*)d_in[3];
    const float* W2  = (const float*)d_in[4];
    const float* fcw = (const float*)d_in[5];
    const float* fcb = (const float*)d_in[6];
    float* out = (float*)d_out;

    cudaFuncSetAttribute(gemm_kernel, cudaFuncAttributeMaxDynamicSharedMemorySize, SMEM_TOTAL);

    packw_kernel<<<(NCOL * DIM + 255) / 256, 256>>>(W1, W2);
    convert_x_kernel<<<NPAD, 128>>>(x);

    dim3 grid(NCOL / BN, NPAD / BM);                       // (8, 392)
    gemm_kernel<<<grid, 256, SMEM_TOTAL>>>(0);             // layer 1 -> g_C
    combine1_kernel<<<NPAD, 128>>>(nb1);                   // -> g_Ahl (bf16 split)
    gemm_kernel<<<grid, 256, SMEM_TOTAL>>>(1);             // layer 2 -> g_C
    combine2_kernel<<<NN, 128>>>(nb2, fcw, out);           // flat -> d_out, FC partials
    final_kernel<<<1, 256>>>(fcb, out + (size_t)(out_size - 2));
}

// round 5
// speedup vs baseline: 3.2837x; 1.3957x over previous
#include <cuda_runtime.h>
#include <cuda_fp16.h>
#include <cstdint>

#define NN 50000
#define NPAD 50176          // 392 * 128
#define DIM 512
#define NCOL 1024
#define K2 1024             // [Ah|Al] x [Bh;Bh]
#define BM 128
#define BN 128
#define BK 64               // fp16 per k-chunk = 128 bytes per row
#define CHUNKS 16           // K2 / BK
#define STAGES 3
#define STAGE_BYTES 32768   // A 16KB + B 16KB
#define SMEM_TOTAL (STAGES * STAGE_BYTES)

typedef unsigned long long ull;

// ---------------- static device scratch (no allocation) ----------------
__device__ __align__(16) __half g_Ahl[(size_t)NPAD * K2];    // 103 MB  [Ah | Al]
__device__ __align__(16) __half g_B1p[NCOL * DIM];           // 1 MB  Bh layer1
__device__ __align__(16) __half g_B2p[NCOL * DIM];           // 1 MB  Bh layer2
__device__ __align__(16) float g_C[(size_t)NPAD * NCOL];     // 205 MB
__device__ float g_part[2 * NN];

// ---------------- PTX helpers ----------------
__device__ __forceinline__ uint32_t smem_u32(const void* p) {
    uint32_t a;
    asm("{ .reg .u64 t; cvta.to.shared.u64 t, %1; cvt.u32.u64 %0, t; }" : "=r"(a) : "l"(p));
    return a;
}
#define CP16(dst, src) asm volatile("cp.async.cg.shared.global [%0], [%1], 16;" :: "r"(dst), "l"(src))
#define CP_COMMIT()    asm volatile("cp.async.commit_group;" ::: "memory")
#define CP_WAIT(n)     asm volatile("cp.async.wait_group %0;" :: "n"(n) : "memory")

#define LDSM_X4(r0, r1, r2, r3, a) \
    asm volatile("ldmatrix.sync.aligned.m8n8.x4.shared.b16 {%0,%1,%2,%3}, [%4];" \
        : "=r"(r0), "=r"(r1), "=r"(r2), "=r"(r3) : "r"(a))

#define MMA16816(c, a, b) \
    asm volatile("mma.sync.aligned.m16n8k16.row.col.f32.f16.f16.f32 " \
        "{%0,%1,%2,%3}, {%4,%5,%6,%7}, {%8,%9}, {%0,%1,%2,%3};" \
        : "+f"((c)[0]), "+f"((c)[1]), "+f"((c)[2]), "+f"((c)[3]) \
        : "r"((a)[0]), "r"((a)[1]), "r"((a)[2]), "r"((a)[3]), "r"((b)[0]), "r"((b)[1]))

// ---------------- split helper: v = h + l, both fp16 (22-bit coverage) -------
__device__ __forceinline__ void split4(const float* v, __half* h, __half* l) {
    #pragma unroll
    for (int q = 0; q < 4; q++) {
        h[q] = __float2half_rn(v[q]);
        l[q] = __float2half_rn(v[q] - __half2float(h[q]));
    }
}

// ---------------- weight pack: Bh[n][k], fp16 ----------------
__global__ void packw_kernel(const float* __restrict__ W1, const float* __restrict__ W2) {
    int idx = blockIdx.x * blockDim.x + threadIdx.x;
    if (idx >= NCOL * DIM) return;
    int n = idx >> 9, k = idx & 511;
    int src = (n < DIM) ? (n * NCOL + k) : ((n - DIM) * NCOL + DIM + k);
    g_B1p[idx] = __float2half_rn(W1[src]);
    g_B2p[idx] = __float2half_rn(W2[src]);
}

// ---------------- convert x -> A' = [Ah | Al] ----------------
__global__ void convert_x_kernel(const float* __restrict__ x) {
    int i = blockIdx.x;
    int j = threadIdx.x * 4;                       // 128 threads cover 512
    __half* row = g_Ahl + (size_t)i * K2;
    if (i >= NN) {
        *(ull*)(row + j) = 0ull; *(ull*)(row + DIM + j) = 0ull;
        return;
    }
    float4 v4 = *(const float4*)(x + (size_t)i * DIM + j);
    float v[4] = {v4.x, v4.y, v4.z, v4.w};
    __half h[4], l[4];
    split4(v, h, l);
    *(ull*)(row + j) = *(ull*)h;
    *(ull*)(row + DIM + j) = *(ull*)l;
}

// ---------------- fp16 HMMA GEMM: g_C[M,1024] = [Ah|Al] @ [Bh;Bh]^T ----------------
// CTA 128x128x64, 3-stage cp.async pipeline, single sync per k-chunk.
__global__ __launch_bounds__(256, 2) void gemm_kernel(int layer) {
    extern __shared__ __align__(1024) char smem[];
    const uint32_t sbase = smem_u32(smem);
    const int tid = threadIdx.x;
    const int wid = tid >> 5;
    const int lane = tid & 31;
    const int wm = wid & 1;           // 2 warps along M
    const int wn = wid >> 1;          // 4 warps along N
    const __half* __restrict__ Bp = layer ? g_B2p : g_B1p;
    const size_t mBase = (size_t)blockIdx.y * BM;
    const int nBase = blockIdx.x * BN;

    const char* gA0 = (const char*)g_Ahl + mBase * (K2 * 2);
    const char* gB0 = (const char*)Bp + (size_t)nBase * (DIM * 2);

    auto load_chunk = [&](int kc, int s) {
        uint32_t sA = sbase + s * STAGE_BYTES;
        uint32_t sB = sA + 16384;
        const char* gA = gA0 + kc * 128;
        const char* gB = gB0 + (kc & 7) * 128;     // B chunks repeat after 8
        #pragma unroll
        for (int i = 0; i < 4; i++) {
            int u = tid + i * 256;            // 0..1023
            int r = u >> 3, c = u & 7;
            uint32_t sw = (uint32_t)(r * 128 + (((c ^ (r & 7))) << 4));
            CP16(sA + sw, gA + (size_t)r * 2048 + c * 16);
            CP16(sB + sw, gB + (size_t)r * 1024 + c * 16);
        }
    };

    float acc[4][4][4];
    #pragma unroll
    for (int i = 0; i < 4; i++)
        #pragma unroll
        for (int j = 0; j < 4; j++)
            #pragma unroll
            for (int q = 0; q < 4; q++) acc[i][j][q] = 0.f;

    load_chunk(0, 0); CP_COMMIT();
    load_chunk(1, 1); CP_COMMIT();

    const int lrow = lane & 15;       // row within 16
    const int lhalf = lane >> 4;      // k-half

    for (int kc = 0; kc < CHUNKS; kc++) {
        CP_WAIT(1);                   // chunk kc resident
        __syncthreads();

        uint32_t sA = sbase + (kc % STAGES) * STAGE_BYTES;
        uint32_t sB = sA + 16384;

        #pragma unroll
        for (int ks = 0; ks < 4; ks++) {
            uint32_t af[4][4], bf[4][2];
            #pragma unroll
            for (int am = 0; am < 4; am++) {
                int row = wm * 64 + am * 16 + lrow;
                int grp = ks * 2 + lhalf;
                uint32_t addr = sA + row * 128 + (((grp ^ (row & 7))) << 4);
                LDSM_X4(af[am][0], af[am][1], af[am][2], af[am][3], addr);
            }
            #pragma unroll
            for (int p = 0; p < 2; p++) {
                int row = wn * 32 + p * 16 + lrow;
                int grp = ks * 2 + lhalf;
                uint32_t addr = sB + row * 128 + (((grp ^ (row & 7))) << 4);
                uint32_t r0, r1, r2, r3;
                LDSM_X4(r0, r1, r2, r3, addr);
                bf[p * 2 + 0][0] = r0; bf[p * 2 + 0][1] = r2;
                bf[p * 2 + 1][0] = r1; bf[p * 2 + 1][1] = r3;
            }
            #pragma unroll
            for (int am = 0; am < 4; am++)
                #pragma unroll
                for (int bn = 0; bn < 4; bn++)
                    MMA16816(acc[am][bn], af[am], bf[bn]);
        }
        // prefetch chunk kc+2 into slot (kc+2)%3 — distinct from slots kc, kc+1;
        // chunk kc-1 readers all passed the barrier above.
        if (kc + 2 < CHUNKS) load_chunk(kc + 2, (kc + 2) % STAGES);
        CP_COMMIT();
    }

    // epilogue: c frag m16n8 -> (row = l>>2 [+8], col = (l&3)*2)
    const int crow = lane >> 2;
    const int ccol = (lane & 3) * 2;
    #pragma unroll
    for (int am = 0; am < 4; am++) {
        size_t r0 = mBase + wm * 64 + am * 16 + crow;
        #pragma unroll
        for (int bn = 0; bn < 4; bn++) {
            int c0 = nBase + wn * 32 + bn * 8 + ccol;
            float* p0 = g_C + r0 * NCOL + c0;
            float* p1 = p0 + 8 * NCOL;
            *(float2*)p0 = make_float2(acc[am][bn][0], acc[am][bn][1]);
            *(float2*)p1 = make_float2(acc[am][bn][2], acc[am][bn][3]);
        }
    }
}

// ---------------- layer-1 combine + fp16 re-split: A' <- relu(Y + 0.5*(Z0+Z1)) ----------------
__global__ void combine1_kernel(const int* __restrict__ neighs) {
    int i = blockIdx.x;
    int j = threadIdx.x * 4;
    __half* row = g_Ahl + (size_t)i * K2;
    if (i >= NN) {
        *(ull*)(row + j) = 0ull; *(ull*)(row + DIM + j) = 0ull;
        return;
    }
    int n0 = neighs[2 * i], n1 = neighs[2 * i + 1];
    float4 s  = *(const float4*)(g_C + (size_t)i  * NCOL + j);
    float4 z0 = *(const float4*)(g_C + (size_t)n0 * NCOL + DIM + j);
    float4 z1 = *(const float4*)(g_C + (size_t)n1 * NCOL + DIM + j);
    float v[4];
    v[0] = fmaxf(fmaf(0.5f, z0.x + z1.x, s.x), 0.f);
    v[1] = fmaxf(fmaf(0.5f, z0.y + z1.y, s.y), 0.f);
    v[2] = fmaxf(fmaf(0.5f, z0.z + z1.z, s.z), 0.f);
    v[3] = fmaxf(fmaf(0.5f, z0.w + z1.w, s.w), 0.f);
    __half h[4], l[4];
    split4(v, h, l);
    *(ull*)(row + j) = *(ull*)h;
    *(ull*)(row + DIM + j) = *(ull*)l;
}

// ---------------- layer-2 combine fused with FC-head partial dots ----------------
__global__ void combine2_kernel(const int* __restrict__ neighs,
                                const float* __restrict__ fcw,
                                float* __restrict__ out) {
    int i = blockIdx.x;
    int tid = threadIdx.x;
    int j = tid * 4;
    int n0 = neighs[2 * i], n1 = neighs[2 * i + 1];
    float4 s  = *(const float4*)(g_C + (size_t)i  * NCOL + j);
    float4 z0 = *(const float4*)(g_C + (size_t)n0 * NCOL + DIM + j);
    float4 z1 = *(const float4*)(g_C + (size_t)n1 * NCOL + DIM + j);
    float4 o;
    o.x = fmaxf(fmaf(0.5f, z0.x + z1.x, s.x), 0.f);
    o.y = fmaxf(fmaf(0.5f, z0.y + z1.y, s.y), 0.f);
    o.z = fmaxf(fmaf(0.5f, z0.z + z1.z, s.z), 0.f);
    o.w = fmaxf(fmaf(0.5f, z0.w + z1.w, s.w), 0.f);
    size_t idx = (size_t)i * DIM + j;
    *(float4*)(out + idx) = o;

    float4 w0 = *(const float4*)(fcw + idx);
    float4 w1 = *(const float4*)(fcw + (size_t)NN * DIM + idx);
    float p0 = o.x * w0.x + o.y * w0.y + o.z * w0.z + o.w * w0.w;
    float p1 = o.x * w1.x + o.y * w1.y + o.z * w1.z + o.w * w1.w;

    __shared__ float s0[128], s1[128];
    s0[tid] = p0; s1[tid] = p1;
    __syncthreads();
    #pragma unroll
    for (int st = 64; st > 0; st >>= 1) {
        if (tid < st) { s0[tid] += s0[tid + st]; s1[tid] += s1[tid + st]; }
        __syncthreads();
    }
    if (tid == 0) { g_part[i] = s0[0]; g_part[NN + i] = s1[0]; }
}

// ---------------- final: deterministic reduce + bias + log_softmax ----------------
__global__ void final_kernel(const float* __restrict__ fcb, float* __restrict__ out2) {
    __shared__ float s0[256], s1[256];
    int tid = threadIdx.x;
    float a = 0.f, b = 0.f;
    for (int i = tid; i < NN; i += 256) { a += g_part[i]; b += g_part[NN + i]; }
    s0[tid] = a; s1[tid] = b;
    __syncthreads();
    #pragma unroll
    for (int st = 128; st > 0; st >>= 1) {
        if (tid < st) { s0[tid] += s0[tid + st]; s1[tid] += s1[tid + st]; }
        __syncthreads();
    }
    if (tid == 0) {
        float l0 = s0[0] + fcb[0];
        float l1 = s1[0] + fcb[1];
        float m = fmaxf(l0, l1);
        float lse = m + logf(expf(l0 - m) + expf(l1 - m));
        out2[0] = l0 - lse;
        out2[1] = l1 - lse;
    }
}

// ---------------- launch ----------------
extern "C" void kernel_launch(void* const* d_in, const int* in_sizes, int n_in,
                              void* d_out, int out_size) {
    const float* x   = (const float*)d_in[0];
    const int*   nb1 = (const int*)  d_in[1];
    const int*   nb2 = (const int*)  d_in[2];
    const float* W1  = (const float*)d_in[3];
    const float* W2  = (const float*)d_in[4];
    const float* fcw = (const float*)d_in[5];
    const float* fcb = (const float*)d_in[6];
    float* out = (float*)d_out;

    cudaFuncSetAttribute(gemm_kernel, cudaFuncAttributeMaxDynamicSharedMemorySize, SMEM_TOTAL);

    packw_kernel<<<(NCOL * DIM + 255) / 256, 256>>>(W1, W2);
    convert_x_kernel<<<NPAD, 128>>>(x);

    dim3 grid(NCOL / BN, NPAD / BM);                       // (8, 392)
    gemm_kernel<<<grid, 256, SMEM_TOTAL>>>(0);             // layer 1 -> g_C
    combine1_kernel<<<NPAD, 128>>>(nb1);                   // -> g_Ahl (fp16 split)
    gemm_kernel<<<grid, 256, SMEM_TOTAL>>>(1);             // layer 2 -> g_C
    combine2_kernel<<<NN, 128>>>(nb2, fcw, out);           // flat -> d_out, FC partials
    final_kernel<<<1, 256>>>(fcb, out + (size_t)(out_size - 2));
}

// round 6
// speedup vs baseline: 5.0673x; 1.5432x over previous
#include <cuda_runtime.h>
#include <cuda_fp16.h>
#include <cstdint>

#define NN 50000
#define NPAD 50176          // 392 * 128
#define DIM 512
#define NCOL 1024
#define BM 128
#define BN 128
#define BK 64               // fp16 per k-chunk = 128 bytes per row
#define CHUNKS 8            // DIM / BK
#define STAGES 3
#define STAGE_BYTES 32768   // A 16KB + B 16KB
#define SMEM_TOTAL (STAGES * STAGE_BYTES)

typedef unsigned long long ull;

// ---------------- static device scratch (no allocation) ----------------
__device__ __align__(16) __half g_Ah[(size_t)NPAD * DIM];    // 51 MB  fp16 A
__device__ __align__(16) __half g_B1p[NCOL * DIM];           // 1 MB  Bh layer1
__device__ __align__(16) __half g_B2p[NCOL * DIM];           // 1 MB  Bh layer2
__device__ __align__(16) float g_C[(size_t)NPAD * NCOL];     // 205 MB
__device__ float g_part[2 * NN];

// ---------------- PTX helpers ----------------
__device__ __forceinline__ uint32_t smem_u32(const void* p) {
    uint32_t a;
    asm("{ .reg .u64 t; cvta.to.shared.u64 t, %1; cvt.u32.u64 %0, t; }" : "=r"(a) : "l"(p));
    return a;
}
#define CP16(dst, src) asm volatile("cp.async.cg.shared.global [%0], [%1], 16;" :: "r"(dst), "l"(src))
#define CP_COMMIT()    asm volatile("cp.async.commit_group;" ::: "memory")
#define CP_WAIT(n)     asm volatile("cp.async.wait_group %0;" :: "n"(n) : "memory")

#define LDSM_X4(r0, r1, r2, r3, a) \
    asm volatile("ldmatrix.sync.aligned.m8n8.x4.shared.b16 {%0,%1,%2,%3}, [%4];" \
        : "=r"(r0), "=r"(r1), "=r"(r2), "=r"(r3) : "r"(a))

#define MMA16816(c, a, b) \
    asm volatile("mma.sync.aligned.m16n8k16.row.col.f32.f16.f16.f32 " \
        "{%0,%1,%2,%3}, {%4,%5,%6,%7}, {%8,%9}, {%0,%1,%2,%3};" \
        : "+f"((c)[0]), "+f"((c)[1]), "+f"((c)[2]), "+f"((c)[3]) \
        : "r"((a)[0]), "r"((a)[1]), "r"((a)[2]), "r"((a)[3]), "r"((b)[0]), "r"((b)[1]))

// ---------------- weight pack: Bh[n][k], fp16 ----------------
__global__ void packw_kernel(const float* __restrict__ W1, const float* __restrict__ W2) {
    int idx = blockIdx.x * blockDim.x + threadIdx.x;
    if (idx >= NCOL * DIM) return;
    int n = idx >> 9, k = idx & 511;
    int src = (n < DIM) ? (n * NCOL + k) : ((n - DIM) * NCOL + DIM + k);
    g_B1p[idx] = __float2half_rn(W1[src]);
    g_B2p[idx] = __float2half_rn(W2[src]);
}

// ---------------- convert x -> fp16 ----------------
__global__ void convert_x_kernel(const float* __restrict__ x) {
    int i = blockIdx.x;
    int j = threadIdx.x * 4;                       // 128 threads cover 512
    __half* row = g_Ah + (size_t)i * DIM;
    if (i >= NN) { *(ull*)(row + j) = 0ull; return; }
    float4 v4 = *(const float4*)(x + (size_t)i * DIM + j);
    __half h[4] = { __float2half_rn(v4.x), __float2half_rn(v4.y),
                    __float2half_rn(v4.z), __float2half_rn(v4.w) };
    *(ull*)(row + j) = *(ull*)h;
}

// ---------------- fp16 HMMA GEMM: g_C[M,1024] = A[M,512] @ B^T ----------------
// CTA 128x128x64, 3-stage cp.async pipeline, single sync per k-chunk.
__global__ __launch_bounds__(256, 2) void gemm_kernel(int layer) {
    extern __shared__ __align__(1024) char smem[];
    const uint32_t sbase = smem_u32(smem);
    const int tid = threadIdx.x;
    const int wid = tid >> 5;
    const int lane = tid & 31;
    const int wm = wid & 1;           // 2 warps along M
    const int wn = wid >> 1;          // 4 warps along N
    const __half* __restrict__ Bp = layer ? g_B2p : g_B1p;
    const size_t mBase = (size_t)blockIdx.y * BM;
    const int nBase = blockIdx.x * BN;

    const char* gA0 = (const char*)g_Ah + mBase * (DIM * 2);
    const char* gB0 = (const char*)Bp + (size_t)nBase * (DIM * 2);

    auto load_chunk = [&](int kc, int s) {
        uint32_t sA = sbase + s * STAGE_BYTES;
        uint32_t sB = sA + 16384;
        const char* gA = gA0 + kc * 128;
        const char* gB = gB0 + kc * 128;
        #pragma unroll
        for (int i = 0; i < 4; i++) {
            int u = tid + i * 256;            // 0..1023
            int r = u >> 3, c = u & 7;
            uint32_t sw = (uint32_t)(r * 128 + (((c ^ (r & 7))) << 4));
            CP16(sA + sw, gA + (size_t)r * 1024 + c * 16);
            CP16(sB + sw, gB + (size_t)r * 1024 + c * 16);
        }
    };

    float acc[4][4][4];
    #pragma unroll
    for (int i = 0; i < 4; i++)
        #pragma unroll
        for (int j = 0; j < 4; j++)
            #pragma unroll
            for (int q = 0; q < 4; q++) acc[i][j][q] = 0.f;

    load_chunk(0, 0); CP_COMMIT();
    load_chunk(1, 1); CP_COMMIT();

    const int lrow = lane & 15;       // row within 16
    const int lhalf = lane >> 4;      // k-half

    for (int kc = 0; kc < CHUNKS; kc++) {
        CP_WAIT(1);                   // chunk kc resident
        __syncthreads();

        uint32_t sA = sbase + (kc % STAGES) * STAGE_BYTES;
        uint32_t sB = sA + 16384;

        #pragma unroll
        for (int ks = 0; ks < 4; ks++) {
            uint32_t af[4][4], bf[4][2];
            #pragma unroll
            for (int am = 0; am < 4; am++) {
                int row = wm * 64 + am * 16 + lrow;
                int grp = ks * 2 + lhalf;
                uint32_t addr = sA + row * 128 + (((grp ^ (row & 7))) << 4);
                LDSM_X4(af[am][0], af[am][1], af[am][2], af[am][3], addr);
            }
            #pragma unroll
            for (int p = 0; p < 2; p++) {
                int row = wn * 32 + p * 16 + lrow;
                int grp = ks * 2 + lhalf;
                uint32_t addr = sB + row * 128 + (((grp ^ (row & 7))) << 4);
                uint32_t r0, r1, r2, r3;
                LDSM_X4(r0, r1, r2, r3, addr);
                bf[p * 2 + 0][0] = r0; bf[p * 2 + 0][1] = r2;
                bf[p * 2 + 1][0] = r1; bf[p * 2 + 1][1] = r3;
            }
            #pragma unroll
            for (int am = 0; am < 4; am++)
                #pragma unroll
                for (int bn = 0; bn < 4; bn++)
                    MMA16816(acc[am][bn], af[am], bf[bn]);
        }
        // prefetch chunk kc+2 into slot (kc+2)%3 — distinct from slots kc, kc+1;
        // chunk kc-1 readers all passed the barrier above.
        if (kc + 2 < CHUNKS) load_chunk(kc + 2, (kc + 2) % STAGES);
        CP_COMMIT();
    }

    // epilogue: c frag m16n8 -> (row = l>>2 [+8], col = (l&3)*2)
    const int crow = lane >> 2;
    const int ccol = (lane & 3) * 2;
    #pragma unroll
    for (int am = 0; am < 4; am++) {
        size_t r0 = mBase + wm * 64 + am * 16 + crow;
        #pragma unroll
        for (int bn = 0; bn < 4; bn++) {
            int c0 = nBase + wn * 32 + bn * 8 + ccol;
            float* p0 = g_C + r0 * NCOL + c0;
            float* p1 = p0 + 8 * NCOL;
            *(float2*)p0 = make_float2(acc[am][bn][0], acc[am][bn][1]);
            *(float2*)p1 = make_float2(acc[am][bn][2], acc[am][bn][3]);
        }
    }
}

// ---------------- layer-1 combine -> fp16: A <- relu(Y + 0.5*(Z0+Z1)) ----------------
__global__ void combine1_kernel(const int* __restrict__ neighs) {
    int i = blockIdx.x;
    int j = threadIdx.x * 4;
    __half* row = g_Ah + (size_t)i * DIM;
    if (i >= NN) { *(ull*)(row + j) = 0ull; return; }
    int n0 = neighs[2 * i], n1 = neighs[2 * i + 1];
    float4 s  = *(const float4*)(g_C + (size_t)i  * NCOL + j);
    float4 z0 = *(const float4*)(g_C + (size_t)n0 * NCOL + DIM + j);
    float4 z1 = *(const float4*)(g_C + (size_t)n1 * NCOL + DIM + j);
    __half h[4];
    h[0] = __float2half_rn(fmaxf(fmaf(0.5f, z0.x + z1.x, s.x), 0.f));
    h[1] = __float2half_rn(fmaxf(fmaf(0.5f, z0.y + z1.y, s.y), 0.f));
    h[2] = __float2half_rn(fmaxf(fmaf(0.5f, z0.z + z1.z, s.z), 0.f));
    h[3] = __float2half_rn(fmaxf(fmaf(0.5f, z0.w + z1.w, s.w), 0.f));
    *(ull*)(row + j) = *(ull*)h;
}

// ---------------- layer-2 combine fused with FC-head partial dots ----------------
__global__ void combine2_kernel(const int* __restrict__ neighs,
                                const float* __restrict__ fcw,
                                float* __restrict__ out) {
    int i = blockIdx.x;
    int tid = threadIdx.x;
    int j = tid * 4;
    int n0 = neighs[2 * i], n1 = neighs[2 * i + 1];
    float4 s  = *(const float4*)(g_C + (size_t)i  * NCOL + j);
    float4 z0 = *(const float4*)(g_C + (size_t)n0 * NCOL + DIM + j);
    float4 z1 = *(const float4*)(g_C + (size_t)n1 * NCOL + DIM + j);
    float4 o;
    o.x = fmaxf(fmaf(0.5f, z0.x + z1.x, s.x), 0.f);
    o.y = fmaxf(fmaf(0.5f, z0.y + z1.y, s.y), 0.f);
    o.z = fmaxf(fmaf(0.5f, z0.z + z1.z, s.z), 0.f);
    o.w = fmaxf(fmaf(0.5f, z0.w + z1.w, s.w), 0.f);
    size_t idx = (size_t)i * DIM + j;
    *(float4*)(out + idx) = o;

    float4 w0 = *(const float4*)(fcw + idx);
    float4 w1 = *(const float4*)(fcw + (size_t)NN * DIM + idx);
    float p0 = o.x * w0.x + o.y * w0.y + o.z * w0.z + o.w * w0.w;
    float p1 = o.x * w1.x + o.y * w1.y + o.z * w1.z + o.w * w1.w;

    __shared__ float s0[128], s1[128];
    s0[tid] = p0; s1[tid] = p1;
    __syncthreads();
    #pragma unroll
    for (int st = 64; st > 0; st >>= 1) {
        if (tid < st) { s0[tid] += s0[tid + st]; s1[tid] += s1[tid + st]; }
        __syncthreads();
    }
    if (tid == 0) { g_part[i] = s0[0]; g_part[NN + i] = s1[0]; }
}

// ---------------- final: deterministic reduce + bias + log_softmax ----------------
__global__ void final_kernel(const float* __restrict__ fcb, float* __restrict__ out2) {
    __shared__ float s0[256], s1[256];
    int tid = threadIdx.x;
    float a = 0.f, b = 0.f;
    for (int i = tid; i < NN; i += 256) { a += g_part[i]; b += g_part[NN + i]; }
    s0[tid] = a; s1[tid] = b;
    __syncthreads();
    #pragma unroll
    for (int st = 128; st > 0; st >>= 1) {
        if (tid < st) { s0[tid] += s0[tid + st]; s1[tid] += s1[tid + st]; }
        __syncthreads();
    }
    if (tid == 0) {
        float l0 = s0[0] + fcb[0];
        float l1 = s1[0] + fcb[1];
        float m = fmaxf(l0, l1);
        float lse = m + logf(expf(l0 - m) + expf(l1 - m));
        out2[0] = l0 - lse;
        out2[1] = l1 - lse;
    }
}

// ---------------- launch ----------------
extern "C" void kernel_launch(void* const* d_in, const int* in_sizes, int n_in,
                              void* d_out, int out_size) {
    const float* x   = (const float*)d_in[0];
    const int*   nb1 = (const int*)  d_in[1];
    const int*   nb2 = (const int*)  d_in[2];
    const float* W1  = (const float*)d_in[3];
    const float* W2  = (const float*)d_in[4];
    const float* fcw = (const float*)d_in[5];
    const float* fcb = (const float*)d_in[6];
    float* out = (float*)d_out;

    cudaFuncSetAttribute(gemm_kernel, cudaFuncAttributeMaxDynamicSharedMemorySize, SMEM_TOTAL);

    packw_kernel<<<(NCOL * DIM + 255) / 256, 256>>>(W1, W2);
    convert_x_kernel<<<NPAD, 128>>>(x);

    dim3 grid(NCOL / BN, NPAD / BM);                       // (8, 392)
    gemm_kernel<<<grid, 256, SMEM_TOTAL>>>(0);             // layer 1 -> g_C
    combine1_kernel<<<NPAD, 128>>>(nb1);                   // -> g_Ah (fp16)
    gemm_kernel<<<grid, 256, SMEM_TOTAL>>>(1);             // layer 2 -> g_C
    combine2_kernel<<<NN, 128>>>(nb2, fcw, out);           // flat -> d_out, FC partials
    final_kernel<<<1, 256>>>(fcb, out + (size_t)(out_size - 2));
}